// round 4
// baseline (speedup 1.0000x reference)
#include <cuda_runtime.h>
#include <cstdint>

// GCNFast folded to ONE GEMM: C[4096,2048] = A[4096,4096] * X[4096,2048]
//   g_A [M,K] = tf32(relu(mask .* GCW))   (K-major)
//   g_XT[N,K] = tf32(h gathered)          (K-major; n=b*128+d, k=t'*64+c)
//   out[b, i%64, i/64, d] = relu(C[i, b*128+d] + GCB[i,d])
// Main kernel: tf32 mma.sync GEMM, conflict-free k-minor SMEM tiles (stride 36),
// 2-stage cp.async double buffer, one __syncthreads per k-tile, 2 CTAs/SM.

namespace {
constexpr int KDIM = 4096, NDIM = 2048, MDIM = 4096;
constexpr int BK = 32;
constexpr int NT = KDIM / BK;                 // 128 k-tiles
constexpr int STRIDE = 36;                    // 32 + 4 pad words
constexpr int TILE = 128 * STRIDE;            // words per tile (A or X)
constexpr int SMEM_BYTES = 2 * 2 * TILE * 4;  // 73728 B
}

__device__ unsigned g_A[(size_t)MDIM * KDIM];    // 64 MB tf32 bits
__device__ unsigned g_XT[(size_t)NDIM * KDIM];   // 32 MB tf32 bits

__device__ __forceinline__ unsigned cvt_tf32(float x) {
    unsigned r;
    asm("cvt.rna.tf32.f32 %0, %1;" : "=r"(r) : "f"(x));
    return r;
}
__device__ __forceinline__ void mma8(float (&c)[4],
                                     unsigned a0, unsigned a1, unsigned a2, unsigned a3,
                                     unsigned b0, unsigned b1) {
    asm volatile(
        "mma.sync.aligned.m16n8k8.row.col.f32.tf32.tf32.f32 "
        "{%0,%1,%2,%3}, {%4,%5,%6,%7}, {%8,%9}, {%0,%1,%2,%3};"
        : "+f"(c[0]), "+f"(c[1]), "+f"(c[2]), "+f"(c[3])
        : "r"(a0), "r"(a1), "r"(a2), "r"(a3), "r"(b0), "r"(b1));
}
__device__ __forceinline__ void cp16(unsigned* dst, const unsigned* src) {
    unsigned s = (unsigned)__cvta_generic_to_shared(dst);
    asm volatile("cp.async.cg.shared.global [%0], [%1], 16;" :: "r"(s), "l"(src));
}

// ---- prep: g_A = tf32(relu(mask * GCW)); mask from 64x64 corner of AA_mask ----
__global__ void __launch_bounds__(256)
prep_A_kernel(const float4* __restrict__ AAm4, const float4* __restrict__ GCW4) {
    size_t idx = (size_t)blockIdx.x * blockDim.x + threadIdx.x;  // 4096*1024 float4s
    int i = (int)(idx >> 10);
    int j4 = (int)(idx & 1023);
    float4 m = AAm4[(size_t)(i & 63) * 1024 + (j4 & 15)];
    float4 w = GCW4[idx];
    uint4 o;
    o.x = cvt_tf32(m.x != 0.f ? fmaxf(w.x, 0.f) : 0.f);
    o.y = cvt_tf32(m.y != 0.f ? fmaxf(w.y, 0.f) : 0.f);
    o.z = cvt_tf32(m.z != 0.f ? fmaxf(w.z, 0.f) : 0.f);
    o.w = cvt_tf32(m.w != 0.f ? fmaxf(w.w, 0.f) : 0.f);
    ((uint4*)g_A)[idx] = o;
}

// ---- prep: g_XT[n,k] = tf32(h[b, k%64, k/64, d]), n = b*128+d ----
__global__ void __launch_bounds__(256)
prep_XT_kernel(const float* __restrict__ h) {
    __shared__ float sm[128][65];
    const int t = blockIdx.x, b = blockIdx.y;
    const int tid = threadIdx.x, lane = tid & 31;
    #pragma unroll
    for (int it = 0; it < 8; ++it) {
        int c = (tid >> 5) + it * 8;
        float4 v = *(const float4*)(h + (((size_t)(b * 64 + c) * 64 + t) << 7) + 4 * lane);
        sm[4 * lane + 0][c] = v.x;
        sm[4 * lane + 1][c] = v.y;
        sm[4 * lane + 2][c] = v.z;
        sm[4 * lane + 3][c] = v.w;
    }
    __syncthreads();
    #pragma unroll
    for (int it = 0; it < 8; ++it) {
        int lin = it * 256 + tid;
        int d = lin >> 4, c4 = lin & 15;
        uint4 o;
        o.x = cvt_tf32(sm[d][4 * c4 + 0]);
        o.y = cvt_tf32(sm[d][4 * c4 + 1]);
        o.z = cvt_tf32(sm[d][4 * c4 + 2]);
        o.w = cvt_tf32(sm[d][4 * c4 + 3]);
        ((uint4*)g_XT)[(size_t)(b * 128 + d) * 1024 + t * 16 + c4] = o;
    }
}

// ---- main GEMM: tf32 mma.sync, conflict-free tiles ----
__global__ void __launch_bounds__(256, 2)
gcn_gemm_kernel(const float* __restrict__ GCB, float* __restrict__ out)
{
    extern __shared__ unsigned smem[];
    unsigned* sA = smem;             // [2][128][STRIDE]  (m-major, k minor)
    unsigned* sX = smem + 2 * TILE;  // [2][128][STRIDE]  (n-major, k minor)

    const int tid = threadIdx.x;
    const int bN = blockIdx.x;   // batch b (N block of 128)
    const int bM = blockIdx.y;   // M block of 128

    const unsigned* gA0 = g_A + (size_t)(bM * 128) * KDIM;
    const unsigned* gX0 = g_XT + (size_t)(bN * 128) * KDIM;

    const int lrow = tid >> 3;          // 0..31? no: tid>>3 = 0..31 for p groups
    const int lc16 = (tid & 7) * 4;     // word offset of 16B chunk

    auto load_tiles = [&](int kt, int st) {
        const int k0 = kt * BK;
        #pragma unroll
        for (int p = 0; p < 4; ++p) {
            int row = lrow + p * 32;
            cp16(sA + st * TILE + row * STRIDE + lc16,
                 gA0 + (size_t)row * KDIM + k0 + lc16);
        }
        #pragma unroll
        for (int p = 0; p < 4; ++p) {
            int row = lrow + p * 32;
            cp16(sX + st * TILE + row * STRIDE + lc16,
                 gX0 + (size_t)row * KDIM + k0 + lc16);
        }
        asm volatile("cp.async.commit_group;" ::: "memory");
    };

    const int lane = tid & 31, wid = tid >> 5;
    const int warpM = wid >> 2;   // 0..1, 64-row M slab
    const int warpN = wid & 3;    // 0..3, 32-col N slab
    const int g = lane >> 2, q = lane & 3;

    // per-thread fragment base offsets (words)
    const unsigned* pA = sA + (warpM * 64 + g) * STRIDE + q;
    const unsigned* pX = sX + (warpN * 32 + g) * STRIDE + q;

    float acc[4][4][4];
    #pragma unroll
    for (int a = 0; a < 4; ++a)
        #pragma unroll
        for (int b = 0; b < 4; ++b)
            #pragma unroll
            for (int v = 0; v < 4; ++v) acc[a][b][v] = 0.f;

    load_tiles(0, 0);

    for (int kt = 0; kt < NT; ++kt) {
        asm volatile("cp.async.wait_group 0;" ::: "memory");
        __syncthreads();
        if (kt + 1 < NT) load_tiles(kt + 1, (kt + 1) & 1);

        const int st = kt & 1;
        const unsigned* tA = pA + st * TILE;
        const unsigned* tX = pX + st * TILE;

        #pragma unroll
        for (int kk = 0; kk < 4; ++kk) {
            unsigned bf[4][2];
            #pragma unroll
            for (int nt = 0; nt < 4; ++nt) {
                bf[nt][0] = tX[nt * 8 * STRIDE + kk * 8];
                bf[nt][1] = tX[nt * 8 * STRIDE + kk * 8 + 4];
            }
            #pragma unroll
            for (int mt = 0; mt < 4; ++mt) {
                unsigned a0 = tA[mt * 16 * STRIDE + kk * 8];
                unsigned a1 = tA[(mt * 16 + 8) * STRIDE + kk * 8];
                unsigned a2 = tA[mt * 16 * STRIDE + kk * 8 + 4];
                unsigned a3 = tA[(mt * 16 + 8) * STRIDE + kk * 8 + 4];
                #pragma unroll
                for (int nt = 0; nt < 4; ++nt)
                    mma8(acc[mt][nt], a0, a1, a2, a3, bf[nt][0], bf[nt][1]);
            }
        }
    }

    // Epilogue: relu(acc + GCB[i,:]) -> out[b, s=i%64, t=i/64, d]
    #pragma unroll
    for (int mt = 0; mt < 4; ++mt) {
        const int i0 = bM * 128 + warpM * 64 + mt * 16 + g;
        #pragma unroll
        for (int r = 0; r < 2; ++r) {
            const int ii = i0 + r * 8;
            const int t = ii >> 6, s = ii & 63;
            float* orow = out + (((size_t)(bN * 64 + s) * 64 + t) << 7);
            const float* brow = GCB + (size_t)ii * 128;
            #pragma unroll
            for (int nt = 0; nt < 4; ++nt) {
                const int d0 = warpN * 32 + nt * 8 + q * 2;
                float2 bias = *(const float2*)(brow + d0);
                float2 v;
                v.x = fmaxf(acc[mt][nt][r * 2 + 0] + bias.x, 0.f);
                v.y = fmaxf(acc[mt][nt][r * 2 + 1] + bias.y, 0.f);
                *(float2*)(orow + d0) = v;
            }
        }
    }
}

extern "C" void kernel_launch(void* const* d_in, const int* in_sizes, int n_in,
                              void* d_out, int out_size) {
    // metadata order: h, e, AA_mask, GCW, GCB
    const float* h   = (const float*)d_in[0];
    const float* AAm = (const float*)d_in[2];
    const float* GCW = (const float*)d_in[3];
    const float* GCB = (const float*)d_in[4];
    float* out = (float*)d_out;

    prep_A_kernel<<<(4096 * 1024) / 256, 256>>>((const float4*)AAm, (const float4*)GCW);
    prep_XT_kernel<<<dim3(64, 16), 256>>>(h);

    cudaFuncSetAttribute(gcn_gemm_kernel,
                         cudaFuncAttributeMaxDynamicSharedMemorySize, SMEM_BYTES);
    dim3 grid(16, 32);
    gcn_gemm_kernel<<<grid, 256, SMEM_BYTES>>>(GCB, out);
}

// round 5
// speedup vs baseline: 2.2945x; 2.2945x over previous
#include <cuda_runtime.h>
#include <cuda_fp16.h>
#include <cstdint>

// GCNFast as ONE fp16 GEMM (fp32 accum): C[4096,2048] = A[4096,4096] * X[4096,2048]
//   g_Af: A = relu(mask .* GCW) in fp16, PRE-PERMUTED into m16n8k16 A-fragment order
//   g_Xf: X gathered from h in fp16, PRE-PERMUTED into B-fragment order
//   out[b, i%64, i/64, d] = relu(C[i, b*128+d] + GCB[i,d])
// Main kernel: mma.sync.m16n8k16.f32.f16.f16.f32; one LDS.128/LDS.64 per fragment;
// cp.async linear block copies; BM=BN=128, BK=64, 2-stage, 2 CTAs/SM.

namespace {
constexpr int KDIM = 4096;
constexpr int NT = KDIM / 64;            // 64 k-tiles of BK=64
constexpr int STAGE = 32768;             // 16KB A + 16KB B per stage
constexpr int SMEM_BYTES = 2 * STAGE;    // 65536
}

// Fragment-major buffers. Block (bM/bN, kt) is a contiguous 16 KB region.
// g_Af block: [kk 0..3][mslab 0..7][lane 0..31] -> uint4 (= regs a0,a1,a2,a3)
// g_Xf block: [kk 0..3][n8 0..15][lane 0..31]  -> uint2 (= regs b0,b1)
__device__ uint4 g_Af[(size_t)32 * 64 * 1024];   // 32 MB
__device__ uint2 g_Xf[(size_t)16 * 64 * 2048];   // 16 MB

__device__ __forceinline__ void mma16(float (&c)[4], const uint4& a, const uint2& b) {
    asm volatile(
        "mma.sync.aligned.m16n8k16.row.col.f32.f16.f16.f32 "
        "{%0,%1,%2,%3}, {%4,%5,%6,%7}, {%8,%9}, {%0,%1,%2,%3};"
        : "+f"(c[0]), "+f"(c[1]), "+f"(c[2]), "+f"(c[3])
        : "r"(a.x), "r"(a.y), "r"(a.z), "r"(a.w), "r"(b.x), "r"(b.y));
}
__device__ __forceinline__ void cp16(void* dst, const void* src) {
    unsigned s = (unsigned)__cvta_generic_to_shared(dst);
    asm volatile("cp.async.cg.shared.global [%0], [%1], 16;" :: "r"(s), "l"(src));
}
__device__ __forceinline__ unsigned packh2(float lo, float hi) {
    __half2 h = __floats2half2_rn(lo, hi);
    return *(unsigned*)&h;
}

// ---- prep A: mask+relu+f16, permute to A-fragment order ----
__global__ void __launch_bounds__(256)
prep_Af_kernel(const float4* __restrict__ AAm4, const float4* __restrict__ GCW4) {
    __shared__ float sm[128][68];
    const int kt = blockIdx.x, bM = blockIdx.y;
    const int tid = threadIdx.x;
    #pragma unroll
    for (int p = 0; p < 8; ++p) {
        int idx = tid + p * 256;                 // 2048 float4s = 128 rows x 16
        int rr = idx >> 4, c4 = idx & 15;
        float4 w = GCW4[(size_t)(bM * 128 + rr) * 1024 + kt * 16 + c4];
        float4 m = AAm4[(size_t)(rr & 63) * 1024 + c4];   // col (kt*64+4c4)&63 = 4c4
        sm[rr][c4 * 4 + 0] = m.x != 0.f ? fmaxf(w.x, 0.f) : 0.f;
        sm[rr][c4 * 4 + 1] = m.y != 0.f ? fmaxf(w.y, 0.f) : 0.f;
        sm[rr][c4 * 4 + 2] = m.z != 0.f ? fmaxf(w.z, 0.f) : 0.f;
        sm[rr][c4 * 4 + 3] = m.w != 0.f ? fmaxf(w.w, 0.f) : 0.f;
    }
    __syncthreads();
    #pragma unroll
    for (int p = 0; p < 4; ++p) {
        int slot = tid + p * 256;                // 1024 fragment slots
        int lane = slot & 31, mslab = (slot >> 5) & 7, kk = slot >> 8;
        int g = lane >> 2, q = lane & 3;
        int r0 = mslab * 16 + g, c0 = kk * 16 + 2 * q;
        uint4 o;
        o.x = packh2(sm[r0][c0],         sm[r0][c0 + 1]);
        o.y = packh2(sm[r0 + 8][c0],     sm[r0 + 8][c0 + 1]);
        o.z = packh2(sm[r0][c0 + 8],     sm[r0][c0 + 9]);
        o.w = packh2(sm[r0 + 8][c0 + 8], sm[r0 + 8][c0 + 9]);
        g_Af[(((size_t)bM * 64 + kt) << 10) + slot] = o;
    }
}

// ---- prep X: gather h, f16, permute to B-fragment order ----
__global__ void __launch_bounds__(256)
prep_Xf_kernel(const float* __restrict__ h) {
    __shared__ float sm[64][132];
    const int kt = blockIdx.x, b = blockIdx.y;   // kt == t' exactly
    const int tid = threadIdx.x;
    #pragma unroll
    for (int p = 0; p < 8; ++p) {
        int idx = tid + p * 256;                 // 2048 float4s = 64 c-rows x 32
        int c = idx >> 5, d4 = idx & 31;
        float4 v = *(const float4*)(h + (((size_t)(b * 64 + c) * 64 + kt) << 7) + d4 * 4);
        sm[c][d4 * 4 + 0] = v.x;
        sm[c][d4 * 4 + 1] = v.y;
        sm[c][d4 * 4 + 2] = v.z;
        sm[c][d4 * 4 + 3] = v.w;
    }
    __syncthreads();
    #pragma unroll
    for (int p = 0; p < 8; ++p) {
        int slot = tid + p * 256;                // 2048 fragment slots
        int lane = slot & 31, n8 = (slot >> 5) & 15, kk = slot >> 9;
        int g = lane >> 2, q = lane & 3;
        int d = n8 * 8 + g, c0 = kk * 16 + 2 * q;
        uint2 o;
        o.x = packh2(sm[c0][d],     sm[c0 + 1][d]);
        o.y = packh2(sm[c0 + 8][d], sm[c0 + 9][d]);
        g_Xf[(((size_t)b * 64 + kt) << 11) + slot] = o;
    }
}

// ---- main GEMM ----
__global__ void __launch_bounds__(256, 2)
gcn_gemm_kernel(const float* __restrict__ GCB, float* __restrict__ out)
{
    extern __shared__ char smem[];
    const int tid = threadIdx.x;
    const int bN = blockIdx.x;   // batch b
    const int bM = blockIdx.y;

    const uint4* gA = g_Af + (((size_t)bM * 64) << 10);
    const uint4* gX = (const uint4*)g_Xf + (((size_t)bN * 64) << 10);

    auto load_tiles = [&](int kt, int st) {
        char* sa = smem + st * STAGE;
        char* sb = sa + 16384;
        #pragma unroll
        for (int p = 0; p < 4; ++p) {
            int ch = tid + p * 256;
            cp16(sa + ch * 16, gA + ((size_t)kt << 10) + ch);
        }
        #pragma unroll
        for (int p = 0; p < 4; ++p) {
            int ch = tid + p * 256;
            cp16(sb + ch * 16, gX + ((size_t)kt << 10) + ch);
        }
        asm volatile("cp.async.commit_group;" ::: "memory");
    };

    const int lane = tid & 31, wid = tid >> 5;
    const int warpM = wid >> 2;   // 0..1
    const int warpN = wid & 3;    // 0..3
    const int g = lane >> 2, q = lane & 3;

    float acc[4][4][4];
    #pragma unroll
    for (int a = 0; a < 4; ++a)
        #pragma unroll
        for (int b = 0; b < 4; ++b)
            #pragma unroll
            for (int v = 0; v < 4; ++v) acc[a][b][v] = 0.f;

    load_tiles(0, 0);

    for (int kt = 0; kt < NT; ++kt) {
        asm volatile("cp.async.wait_group 0;" ::: "memory");
        __syncthreads();
        if (kt + 1 < NT) load_tiles(kt + 1, (kt + 1) & 1);

        const char* sa = smem + (kt & 1) * STAGE;
        const char* sb = sa + 16384;

        #pragma unroll
        for (int kk = 0; kk < 4; ++kk) {
            uint2 bf[4];
            #pragma unroll
            for (int nt = 0; nt < 4; ++nt)
                bf[nt] = *(const uint2*)(sb + (((kk * 16 + warpN * 4 + nt) * 32 + lane) << 3));
            #pragma unroll
            for (int mt = 0; mt < 4; ++mt) {
                uint4 af = *(const uint4*)(sa + (((kk * 8 + warpM * 4 + mt) * 32 + lane) << 4));
                #pragma unroll
                for (int nt = 0; nt < 4; ++nt)
                    mma16(acc[mt][nt], af, bf[nt]);
            }
        }
    }

    // Epilogue: relu(acc + GCB[i,:]) -> out[b, s=i%64, t=i/64, d]
    #pragma unroll
    for (int mt = 0; mt < 4; ++mt) {
        const int i0 = bM * 128 + warpM * 64 + mt * 16 + g;
        #pragma unroll
        for (int r = 0; r < 2; ++r) {
            const int ii = i0 + r * 8;
            const int t = ii >> 6, s = ii & 63;
            float* orow = out + (((size_t)(bN * 64 + s) * 64 + t) << 7);
            const float* brow = GCB + (size_t)ii * 128;
            #pragma unroll
            for (int nt = 0; nt < 4; ++nt) {
                const int d0 = warpN * 32 + nt * 8 + q * 2;
                float2 bias = *(const float2*)(brow + d0);
                float2 v;
                v.x = fmaxf(acc[mt][nt][r * 2 + 0] + bias.x, 0.f);
                v.y = fmaxf(acc[mt][nt][r * 2 + 1] + bias.y, 0.f);
                *(float2*)(orow + d0) = v;
            }
        }
    }
}

extern "C" void kernel_launch(void* const* d_in, const int* in_sizes, int n_in,
                              void* d_out, int out_size) {
    // metadata order: h, e, AA_mask, GCW, GCB
    const float* h   = (const float*)d_in[0];
    const float* AAm = (const float*)d_in[2];
    const float* GCW = (const float*)d_in[3];
    const float* GCB = (const float*)d_in[4];
    float* out = (float*)d_out;

    prep_Af_kernel<<<dim3(64, 32), 256>>>((const float4*)AAm, (const float4*)GCW);
    prep_Xf_kernel<<<dim3(64, 16), 256>>>(h);

    cudaFuncSetAttribute(gcn_gemm_kernel,
                         cudaFuncAttributeMaxDynamicSharedMemorySize, SMEM_BYTES);
    dim3 grid(16, 32);
    gcn_gemm_kernel<<<grid, 256, SMEM_BYTES>>>(GCB, out);
}